// round 2
// baseline (speedup 1.0000x reference)
#include <cuda_runtime.h>
#include <math.h>
#include <float.h>

// ---------------- scratch (device globals; no allocs allowed) ----------------
__device__ float g_a1[33554432];  // [8,64,256,256] enc1 out / dec convT2 out
__device__ float g_a2[8388608];   // [8,64,128,128] enc2 out / dec convT1 out
__device__ float g_a3[2097152];   // [8,64,64,64]   enc3 out
__device__ float g_z [2097152];   // [8,64,64,64]   encoder z
__device__ float g_zq[2097152];   // [8,64,64,64]   quantized z
__device__ float g_d1[2097152];   // [8,64,64,64]   dec conv1 out
__device__ float g_dmin[32768];   // per-position min distance
__device__ float g_e2[512];       // codebook row norms

__device__ __forceinline__ float* g_buf(int s) {
    switch (s) {
        case 1: return g_a1;
        case 2: return g_a2;
        case 3: return g_a3;
        case 4: return g_z;
        case 5: return g_zq;
        case 6: return g_d1;
    }
    return nullptr;
}

// ---------------- conv1: cin=1, k4 s2 p1, 1->64, relu, 512->256 ----------------
__global__ void k_conv1(const float* __restrict__ x, const float* __restrict__ w,
                        const float* __restrict__ bias)
{
    __shared__ float sw[1024];
    __shared__ float sb[64];
    const int tid = threadIdx.x;
    for (int i = tid; i < 1024; i += 256) sw[i] = w[i];
    if (tid < 64) sb[tid] = bias[tid];
    __syncthreads();

    const int gid = blockIdx.x * 256 + tid;      // 8*256*256 total
    const int ox = gid & 255;
    const int oy = (gid >> 8) & 255;
    const int b  = gid >> 16;
    const int iy0 = oy * 2 - 1, ix0 = ox * 2 - 1;
    const float* xb = x + (size_t)b * 512 * 512;

    float v[16];
#pragma unroll
    for (int ky = 0; ky < 4; ky++) {
#pragma unroll
        for (int kx = 0; kx < 4; kx++) {
            int iy = iy0 + ky, ix = ix0 + kx;
            float t = 0.f;
            if ((unsigned)iy < 512u && (unsigned)ix < 512u) t = xb[iy * 512 + ix];
            v[ky * 4 + kx] = t;
        }
    }
    float* ob = g_a1 + (size_t)b * 64 * 65536 + oy * 256 + ox;
#pragma unroll 4
    for (int co = 0; co < 64; co++) {
        float a = sb[co];
#pragma unroll
        for (int t = 0; t < 16; t++) a += v[t] * sw[co * 16 + t];
        ob[(size_t)co * 65536] = fmaxf(a, 0.f);
    }
}

// ---------------- generic k4 s2 p1, 64->64, relu; 32x32 output tile ----------------
__global__ void k_conv4x4s2(int in_sel, const float* __restrict__ w,
                            const float* __restrict__ bias, int out_sel,
                            int Hin, int Win)
{
    __shared__ float s_in[66 * 67];
    __shared__ float s_w[128];
    const float* in = g_buf(in_sel);
    float* out = g_buf(out_sel);

    const int tid = threadIdx.x;
    const int tx = tid & 15, ty = tid >> 4;
    const int b   = blockIdx.z >> 3;
    const int co0 = (blockIdx.z & 7) << 3;
    const int oy0 = blockIdx.y << 5, ox0 = blockIdx.x << 5;
    const int iy0 = (oy0 << 1) - 1, ix0 = (ox0 << 1) - 1;
    const int Hout = Hin >> 1, Wout = Win >> 1;
    const float* inb = in + (size_t)b * 64 * Hin * Win;

    float acc[4][8];
#pragma unroll
    for (int p = 0; p < 4; p++)
#pragma unroll
        for (int c = 0; c < 8; c++) acc[p][c] = 0.f;

    for (int ci = 0; ci < 64; ci++) {
        __syncthreads();
        const float* ic = inb + (size_t)ci * Hin * Win;
        for (int i = tid; i < 66 * 66; i += 256) {
            int r = i / 66, c = i - r * 66;
            int iy = iy0 + r, ix = ix0 + c;
            float t = 0.f;
            if ((unsigned)iy < (unsigned)Hin && (unsigned)ix < (unsigned)Win)
                t = ic[iy * Win + ix];
            s_in[r * 67 + c] = t;
        }
        if (tid < 128)
            s_w[tid] = w[(((co0 + (tid >> 4)) * 64) + ci) * 16 + (tid & 15)];
        __syncthreads();

#pragma unroll
        for (int ky = 0; ky < 4; ky++) {
#pragma unroll
            for (int kx = 0; kx < 4; kx++) {
                float v00 = s_in[(4 * ty + ky) * 67 + 4 * tx + kx];
                float v01 = s_in[(4 * ty + ky) * 67 + 4 * tx + kx + 2];
                float v10 = s_in[(4 * ty + ky + 2) * 67 + 4 * tx + kx];
                float v11 = s_in[(4 * ty + ky + 2) * 67 + 4 * tx + kx + 2];
#pragma unroll
                for (int co = 0; co < 8; co++) {
                    float wv = s_w[(co << 4) + (ky << 2) + kx];
                    acc[0][co] += v00 * wv;
                    acc[1][co] += v01 * wv;
                    acc[2][co] += v10 * wv;
                    acc[3][co] += v11 * wv;
                }
            }
        }
    }

#pragma unroll
    for (int co = 0; co < 8; co++) {
        float bv = bias[co0 + co];
        float* ob = out + ((size_t)(b * 64 + co0 + co) * Hout + oy0) * Wout + ox0;
#pragma unroll
        for (int dy = 0; dy < 2; dy++)
#pragma unroll
            for (int dx = 0; dx < 2; dx++) {
                float v = acc[dy * 2 + dx][co] + bv;
                ob[(2 * ty + dy) * Wout + 2 * tx + dx] = fmaxf(v, 0.f);
            }
    }
}

// ---------------- k3 s1 p1, 64->64 on 64x64 images; optional relu ----------------
__global__ void k_conv3x3(int in_sel, const float* __restrict__ w,
                          const float* __restrict__ bias, int out_sel, int do_relu)
{
    __shared__ float s_in[34 * 35];
    __shared__ float s_w[72];
    const float* in = g_buf(in_sel);
    float* out = g_buf(out_sel);

    const int tid = threadIdx.x;
    const int tx = tid & 15, ty = tid >> 4;
    const int b   = blockIdx.z >> 3;
    const int co0 = (blockIdx.z & 7) << 3;
    const int oy0 = blockIdx.y << 5, ox0 = blockIdx.x << 5;
    const int iy0 = oy0 - 1, ix0 = ox0 - 1;
    const float* inb = in + (size_t)b * 64 * 4096;

    float acc[4][8];
#pragma unroll
    for (int p = 0; p < 4; p++)
#pragma unroll
        for (int c = 0; c < 8; c++) acc[p][c] = 0.f;

    for (int ci = 0; ci < 64; ci++) {
        __syncthreads();
        const float* ic = inb + ci * 4096;
        for (int i = tid; i < 34 * 34; i += 256) {
            int r = i / 34, c = i - r * 34;
            int iy = iy0 + r, ix = ix0 + c;
            float t = 0.f;
            if ((unsigned)iy < 64u && (unsigned)ix < 64u) t = ic[(iy << 6) + ix];
            s_in[r * 35 + c] = t;
        }
        if (tid < 72)
            s_w[tid] = w[(((co0 + tid / 9) * 64) + ci) * 9 + (tid % 9)];
        __syncthreads();

#pragma unroll
        for (int ky = 0; ky < 3; ky++) {
#pragma unroll
            for (int kx = 0; kx < 3; kx++) {
                float v00 = s_in[(2 * ty + ky) * 35 + 2 * tx + kx];
                float v01 = s_in[(2 * ty + ky) * 35 + 2 * tx + kx + 1];
                float v10 = s_in[(2 * ty + ky + 1) * 35 + 2 * tx + kx];
                float v11 = s_in[(2 * ty + ky + 1) * 35 + 2 * tx + kx + 1];
#pragma unroll
                for (int co = 0; co < 8; co++) {
                    float wv = s_w[co * 9 + ky * 3 + kx];
                    acc[0][co] += v00 * wv;
                    acc[1][co] += v01 * wv;
                    acc[2][co] += v10 * wv;
                    acc[3][co] += v11 * wv;
                }
            }
        }
    }

#pragma unroll
    for (int co = 0; co < 8; co++) {
        float bv = bias[co0 + co];
        float* ob = out + ((size_t)(b * 64 + co0 + co) * 64 + oy0) * 64 + ox0;
#pragma unroll
        for (int dy = 0; dy < 2; dy++)
#pragma unroll
            for (int dx = 0; dx < 2; dx++) {
                float v = acc[dy * 2 + dx][co] + bv;
                if (do_relu) v = fmaxf(v, 0.f);
                ob[(2 * ty + dy) * 64 + 2 * tx + dx] = v;
            }
    }
}

// ---------------- convT k4 s2 p1 (torch layout [Cin,Cout,4,4]), 64->64, relu -----
__global__ void k_convt(int in_sel, const float* __restrict__ w,
                        const float* __restrict__ bias, int out_sel,
                        int Hin, int Win)
{
    __shared__ float s_in[18 * 19];
    __shared__ float s_w[128];
    const float* in = g_buf(in_sel);
    float* out = g_buf(out_sel);

    const int tid = threadIdx.x;
    const int tx = tid & 15, ty = tid >> 4;
    const int b   = blockIdx.z >> 3;
    const int co0 = (blockIdx.z & 7) << 3;
    const int oy0 = blockIdx.y << 5, ox0 = blockIdx.x << 5;
    const int iy0 = (oy0 >> 1) - 1, ix0 = (ox0 >> 1) - 1;
    const int Hout = Hin << 1, Wout = Win << 1;
    const float* inb = in + (size_t)b * 64 * Hin * Win;

    float acc[4][8];
#pragma unroll
    for (int p = 0; p < 4; p++)
#pragma unroll
        for (int c = 0; c < 8; c++) acc[p][c] = 0.f;

    for (int ci = 0; ci < 64; ci++) {
        __syncthreads();
        const float* ic = inb + (size_t)ci * Hin * Win;
        for (int i = tid; i < 18 * 18; i += 256) {
            int r = i / 18, c = i - r * 18;
            int iy = iy0 + r, ix = ix0 + c;
            float t = 0.f;
            if ((unsigned)iy < (unsigned)Hin && (unsigned)ix < (unsigned)Win)
                t = ic[iy * Win + ix];
            s_in[r * 19 + c] = t;
        }
        if (tid < 128)
            s_w[tid] = w[((ci * 64) + co0 + (tid >> 4)) * 16 + (tid & 15)];
        __syncthreads();

        float v[3][3];
#pragma unroll
        for (int r = 0; r < 3; r++)
#pragma unroll
            for (int c = 0; c < 3; c++)
                v[r][c] = s_in[(ty + r) * 19 + tx + c];

        // out(oy,ox): iy=(oy+1-ky)/2 valid when parity matches.
        // dy = 1-(ky&1), local row offset rr = (4-ky)>>1 (same for kx).
#pragma unroll
        for (int ky = 0; ky < 4; ky++) {
            const int dy = 1 - (ky & 1);
            const int rr = (4 - ky) >> 1;
#pragma unroll
            for (int kx = 0; kx < 4; kx++) {
                const int dx = 1 - (kx & 1);
                const int cc = (4 - kx) >> 1;
                float vv = v[rr][cc];
#pragma unroll
                for (int co = 0; co < 8; co++)
                    acc[dy * 2 + dx][co] += vv * s_w[(co << 4) + (ky << 2) + kx];
            }
        }
    }

#pragma unroll
    for (int co = 0; co < 8; co++) {
        float bv = bias[co0 + co];
        float* ob = out + ((size_t)(b * 64 + co0 + co) * Hout + oy0) * Wout + ox0;
#pragma unroll
        for (int dy = 0; dy < 2; dy++)
#pragma unroll
            for (int dx = 0; dx < 2; dx++) {
                float v2 = acc[dy * 2 + dx][co] + bv;
                ob[(2 * ty + dy) * Wout + 2 * tx + dx] = fmaxf(v2, 0.f);
            }
    }
}

// ---------------- convT3: 64->1, sigmoid, 256->512, writes d_out ----------------
__global__ void k_convt_out(const float* __restrict__ w,
                            const float* __restrict__ bias, float* __restrict__ out)
{
    __shared__ float s_in[18 * 19];
    __shared__ float s_w[16];
    const int tid = threadIdx.x;
    const int tx = tid & 15, ty = tid >> 4;
    const int b = blockIdx.z;
    const int oy0 = blockIdx.y << 5, ox0 = blockIdx.x << 5;
    const int iy0 = (oy0 >> 1) - 1, ix0 = (ox0 >> 1) - 1;
    const float* inb = g_a1 + (size_t)b * 64 * 65536;   // Hin=Win=256

    float acc[4] = {0.f, 0.f, 0.f, 0.f};

    for (int ci = 0; ci < 64; ci++) {
        __syncthreads();
        const float* ic = inb + (size_t)ci * 65536;
        for (int i = tid; i < 18 * 18; i += 256) {
            int r = i / 18, c = i - r * 18;
            int iy = iy0 + r, ix = ix0 + c;
            float t = 0.f;
            if ((unsigned)iy < 256u && (unsigned)ix < 256u) t = ic[(iy << 8) + ix];
            s_in[r * 19 + c] = t;
        }
        if (tid < 16) s_w[tid] = w[ci * 16 + tid];   // [Cin,1,4,4]
        __syncthreads();

        float v[3][3];
#pragma unroll
        for (int r = 0; r < 3; r++)
#pragma unroll
            for (int c = 0; c < 3; c++)
                v[r][c] = s_in[(ty + r) * 19 + tx + c];

#pragma unroll
        for (int ky = 0; ky < 4; ky++) {
            const int dy = 1 - (ky & 1);
            const int rr = (4 - ky) >> 1;
#pragma unroll
            for (int kx = 0; kx < 4; kx++) {
                const int dx = 1 - (kx & 1);
                const int cc = (4 - kx) >> 1;
                acc[dy * 2 + dx] += v[rr][cc] * s_w[(ky << 2) + kx];
            }
        }
    }

    float bv = bias[0];
#pragma unroll
    for (int dy = 0; dy < 2; dy++)
#pragma unroll
        for (int dx = 0; dx < 2; dx++) {
            float s = acc[dy * 2 + dx] + bv;
            s = 1.f / (1.f + expf(-s));
            out[((size_t)b * 512 + oy0 + 2 * ty + dy) * 512 + ox0 + 2 * tx + dx] = s;
        }
}

// ---------------- VQ ----------------
__global__ void k_e2(const float* __restrict__ cb)
{
    int k = threadIdx.x;   // 512 threads
    float s = 0.f;
    for (int c = 0; c < 64; c++) {
        float v = cb[k * 64 + c];
        s += v * v;
    }
    g_e2[k] = s;
}

// 32 positions per block, 256 threads. Codebook staged in 64-code chunks.
__global__ void k_vq(const float* __restrict__ cb)
{
    __shared__ float s_z[32 * 65];
    __shared__ float s_cb[64 * 65];
    __shared__ float s_z2[32];
    __shared__ float s_bd[32];
    __shared__ int   s_bk[32];

    const int tid = threadIdx.x;
    const int pos0 = blockIdx.x * 32;
    const int b = pos0 >> 12;          // 4096 positions per batch image
    const int hw0 = pos0 & 4095;
    const float* zb = g_z + (size_t)b * 262144;

    // load 32 z vectors: thread t -> pos t&31, channels (t>>5)*8..+8
    {
        int pl = tid & 31, cb8 = tid >> 5;
        for (int cc = 0; cc < 8; cc++) {
            int c = cb8 * 8 + cc;
            s_z[pl * 65 + c] = zb[(size_t)c * 4096 + hw0 + pl];
        }
    }
    __syncthreads();
    if (tid < 32) {
        float s = 0.f;
        for (int c = 0; c < 64; c++) { float t = s_z[tid * 65 + c]; s += t * t; }
        s_z2[tid] = s;
    }

    const int j = tid & 7;    // code sub-lane
    const int p = tid >> 3;   // position 0..31
    float best_d = FLT_MAX;
    int best_k = 0;

    for (int chunk = 0; chunk < 8; chunk++) {
        __syncthreads();
        for (int i = tid; i < 4096; i += 256) {
            int code = i >> 6, c = i & 63;
            s_cb[code * 65 + c] = cb[chunk * 4096 + i];
        }
        __syncthreads();

        float dot[8];
#pragma unroll
        for (int jj = 0; jj < 8; jj++) dot[jj] = 0.f;
        for (int c = 0; c < 64; c++) {
            float zc = s_z[p * 65 + c];
#pragma unroll
            for (int jj = 0; jj < 8; jj++)
                dot[jj] += zc * s_cb[(j + 8 * jj) * 65 + c];
        }
#pragma unroll
        for (int jj = 0; jj < 8; jj++) {
            int k = chunk * 64 + j + 8 * jj;
            float d = g_e2[k] - 2.f * dot[jj];
            if (d < best_d || (d == best_d && k < best_k)) { best_d = d; best_k = k; }
        }
    }

    // reduce over the 8 threads sharing a position (contiguous lanes)
#pragma unroll
    for (int off = 4; off; off >>= 1) {
        float od = __shfl_down_sync(0xffffffffu, best_d, off);
        int   ok = __shfl_down_sync(0xffffffffu, best_k, off);
        if (od < best_d || (od == best_d && ok < best_k)) { best_d = od; best_k = ok; }
    }
    if (j == 0) { s_bd[p] = best_d; s_bk[p] = best_k; }
    __syncthreads();

    if (tid < 32) g_dmin[pos0 + tid] = s_z2[tid] + s_bd[tid];

    // gather z_q (coalesced along hw)
    {
        int pl = tid & 31, cb8 = tid >> 5;
        float* zqb = g_zq + (size_t)b * 262144;
        int kidx = s_bk[pl];
        for (int cc = 0; cc < 8; cc++) {
            int c = cb8 * 8 + cc;
            zqb[(size_t)c * 4096 + hw0 + pl] = cb[kidx * 64 + c];
        }
    }
}

__global__ void k_loss(float* __restrict__ out_loss)
{
    __shared__ float sm[1024];
    int tid = threadIdx.x;
    float s = 0.f;
    for (int i = tid; i < 32768; i += 1024) s += g_dmin[i];
    sm[tid] = s;
    __syncthreads();
    for (int off = 512; off; off >>= 1) {
        if (tid < off) sm[tid] += sm[tid + off];
        __syncthreads();
    }
    if (tid == 0) out_loss[0] = sm[0] * (1.25f / 2097152.f);
}

// ---------------- launch ----------------
extern "C" void kernel_launch(void* const* d_in, const int* in_sizes, int n_in,
                              void* d_out, int out_size)
{
    const float* x   = (const float*)d_in[0];
    const float* ew1 = (const float*)d_in[1];
    const float* eb1 = (const float*)d_in[2];
    const float* ew2 = (const float*)d_in[3];
    const float* eb2 = (const float*)d_in[4];
    const float* ew3 = (const float*)d_in[5];
    const float* eb3 = (const float*)d_in[6];
    const float* ew4 = (const float*)d_in[7];
    const float* eb4 = (const float*)d_in[8];
    const float* cb  = (const float*)d_in[9];
    const float* dw1 = (const float*)d_in[10];
    const float* db1 = (const float*)d_in[11];
    const float* tw1 = (const float*)d_in[12];
    const float* tb1 = (const float*)d_in[13];
    const float* tw2 = (const float*)d_in[14];
    const float* tb2 = (const float*)d_in[15];
    const float* tw3 = (const float*)d_in[16];
    const float* tb3 = (const float*)d_in[17];
    float* out = (float*)d_out;

    // encoder
    k_e2<<<1, 512>>>(cb);
    k_conv1<<<2048, 256>>>(x, ew1, eb1);                                  // x -> a1
    k_conv4x4s2<<<dim3(4, 4, 64), 256>>>(1, ew2, eb2, 2, 256, 256);       // a1 -> a2
    k_conv4x4s2<<<dim3(2, 2, 64), 256>>>(2, ew3, eb3, 3, 128, 128);       // a2 -> a3
    k_conv3x3<<<dim3(2, 2, 64), 256>>>(3, ew4, eb4, 4, 0);                // a3 -> z

    // vector quantizer
    k_vq<<<1024, 256>>>(cb);                                              // z -> zq, dmin
    k_loss<<<1, 1024>>>(out + (out_size - 1));

    // decoder
    k_conv3x3<<<dim3(2, 2, 64), 256>>>(5, dw1, db1, 6, 1);                // zq -> d1
    k_convt<<<dim3(4, 4, 64), 256>>>(6, tw1, tb1, 2, 64, 64);             // d1 -> a2 (128^2)
    k_convt<<<dim3(8, 8, 64), 256>>>(2, tw2, tb2, 1, 128, 128);           // a2 -> a1 (256^2)
    k_convt_out<<<dim3(16, 16, 8), 256>>>(tw3, tb3, out);                 // a1 -> x_hat
}